// round 6
// baseline (speedup 1.0000x reference)
#include <cuda_runtime.h>
#include <cstdint>

#define CODEBOOK 32768
#define NTOK     9216      // 1*4*48*48 tokens
#define CH_STRIDE 2304     // 48*48
#define T_STRIDE  9216     // 4 channels * 2304

#define TPB     128
#define TPT     4                           // tokens per thread (2 f32x2 pairs)
#define CHUNKS  32
#define CHUNK   (CODEBOOK / CHUNKS)         // 1024 codes per chunk
#define GROUP   16
#define NGROUP  (CHUNK / GROUP)             // 64 groups per chunk
#define TOKBLKS (NTOK / (TPB * TPT))        // 18 token blocks
#define FIXBLKS 296

// Scratch (static __device__ — no allocation)
__device__ ulonglong2          g_pkA[CODEBOOK];   // (e0,e0) (e1,e1) packed f32x2
__device__ ulonglong2          g_pkB[CODEBOOK];   // (e2,e2) (e3,e3)
__device__ unsigned long long  g_best[NTOK];      // (ford(s_g) << 32) | global_group_id
__device__ unsigned int        g_slow[NTOK];      // 1 if xs < 0.125 (needs exact t per code)

// ---------- packed f32x2 helpers ----------
static __device__ __forceinline__ unsigned long long pack2(float lo, float hi) {
    unsigned long long r;
    asm("mov.b64 %0,{%1,%2};" : "=l"(r) : "f"(lo), "f"(hi));
    return r;
}
static __device__ __forceinline__ unsigned long long mul2(unsigned long long a, unsigned long long b) {
    unsigned long long d;
    asm("mul.rn.f32x2 %0,%1,%2;" : "=l"(d) : "l"(a), "l"(b));
    return d;
}
static __device__ __forceinline__ unsigned long long add2(unsigned long long a, unsigned long long b) {
    unsigned long long d;
    asm("add.rn.f32x2 %0,%1,%2;" : "=l"(d) : "l"(a), "l"(b));
    return d;
}
// lo/hi = a + b per half, unpacked to scalars (mov.b64 split is register renaming)
static __device__ __forceinline__ void add2_unpack(unsigned long long a, unsigned long long b,
                                                   float& lo, float& hi) {
    asm("{\n\t"
        ".reg .b64 t;\n\t"
        "add.rn.f32x2 t,%2,%3;\n\t"
        "mov.b64 {%0,%1},t;\n\t"
        "}" : "=f"(lo), "=f"(hi) : "l"(a), "l"(b));
}

// scores are positive finite; ford is monotone there
static __device__ __forceinline__ unsigned int ford(float v) {
    return __float_as_uint(v) | 0x80000000u;
}

static __device__ __forceinline__ float token_xs(const float* p, float& x0, float& x1,
                                                 float& x2, float& x3) {
    x0 = __ldg(p); x1 = __ldg(p + CH_STRIDE);
    x2 = __ldg(p + 2 * CH_STRIDE); x3 = __ldg(p + 3 * CH_STRIDE);
    return __fadd_rn(__fadd_rn(__fadd_rn(__fmul_rn(x0, x0), __fmul_rn(x1, x1)),
                               __fmul_rn(x2, x2)), __fmul_rn(x3, x3));
}

// exact reference score: s = fl(fl(xs+e2) - 2*fl_leftassoc_dot)
static __device__ __forceinline__ float exact_score(float x0, float x1, float x2, float x3,
                                                    float xs, float4 e) {
    const float e2 = __fadd_rn(__fadd_rn(__fadd_rn(__fmul_rn(e.x, e.x), __fmul_rn(e.y, e.y)),
                                         __fmul_rn(e.z, e.z)), __fmul_rn(e.w, e.w));
    const float dot = __fadd_rn(__fadd_rn(__fadd_rn(__fmul_rn(x0, e.x), __fmul_rn(x1, e.y)),
                                          __fmul_rn(x2, e.z)), __fmul_rn(x3, e.w));
    return __fmaf_rn(-2.0f, dot, __fadd_rn(xs, e2));
}

// ---------- kernel 1: codebook transform + scratch init + slow-token flags ----------
__global__ void vq_prep(const float4* __restrict__ emb, const float* __restrict__ hs) {
    int k = blockIdx.x * blockDim.x + threadIdx.x;
    if (k < NTOK) {
        g_best[k] = ~0ull;
        const int t = k / CH_STRIDE, hw = k % CH_STRIDE;
        float x0, x1, x2, x3;
        const float xs = token_xs(hs + t * T_STRIDE + hw, x0, x1, x2, x3);
        // xs >= 0.125 guarantees fl(xs + e2) == xs for all codes (e2 <= 2^-28 < ulp/2)
        g_slow[k] = (xs < 0.125f) ? 1u : 0u;
    }
    if (k < CODEBOOK) {
        float4 e = __ldg(&emb[k]);
        g_pkA[k] = make_ulonglong2(pack2(e.x, e.x), pack2(e.y, e.y));
        g_pkB[k] = make_ulonglong2(pack2(e.z, e.z), pack2(e.w, e.w));
    }
}

// ---------- kernel 2: main scan (dot-max per group; score once per group) ----------
// blockIdx.x : token group (512 tokens, 4/thread), blockIdx.y : codebook chunk (1024 codes)
__global__ void __launch_bounds__(TPB) vq_main(const float* __restrict__ hs) {
    const int tid     = threadIdx.x;
    const int tokbase = blockIdx.x * (TPB * TPT);
    const int base    = blockIdx.y * CHUNK;

    float x[4][TPT], xs[TPT];
#pragma unroll
    for (int h = 0; h < TPT; h++) {
        const int n = tokbase + h * TPB + tid;
        const int t = n / CH_STRIDE, hw = n % CH_STRIDE;
        xs[h] = token_xs(hs + t * T_STRIDE + hw, x[0][h], x[1][h], x[2][h], x[3][h]);
    }

    unsigned long long X0[2], X1[2], X2[2], X3[2];
#pragma unroll
    for (int p2 = 0; p2 < 2; p2++) {
        X0[p2] = pack2(x[0][2 * p2], x[0][2 * p2 + 1]);
        X1[p2] = pack2(x[1][2 * p2], x[1][2 * p2 + 1]);
        X2[p2] = pack2(x[2][2 * p2], x[2][2 * p2 + 1]);
        X3[p2] = pack2(x[3][2 * p2], x[3][2 * p2 + 1]);
    }
    const float INF = __int_as_float(0x7f800000);
    const float NINF = __int_as_float(0xff800000);

    float m[TPT]    = {INF, INF, INF, INF};   // running min group-score
    int   gsel[TPT] = {0, 0, 0, 0};           // earliest group achieving it

    for (int g = 0; g < NGROUP; g++) {
        float dm[TPT] = {NINF, NINF, NINF, NINF};   // group dot max per token
#pragma unroll
        for (int u = 0; u < GROUP; u++) {
            const int k = base + g * GROUP + u;
            const ulonglong2 A = g_pkA[k];
            const ulonglong2 B = g_pkB[k];
#pragma unroll
            for (int p2 = 0; p2 < 2; p2++) {
                // dot = ((x0*e0 + x1*e1) + x2*e2) + x3*e3, per-half rn (matches reference)
                unsigned long long d = add2(mul2(X0[p2], A.x), mul2(X1[p2], A.y));
                d = add2(d, mul2(X2[p2], B.x));
                float d0, d1;
                add2_unpack(d, mul2(X3[p2], B.y), d0, d1);
                dm[2 * p2]     = fmaxf(dm[2 * p2], d0);
                dm[2 * p2 + 1] = fmaxf(dm[2 * p2 + 1], d1);
            }
        }
        // group min score = fl(xs - 2*dmax) (monotone; exact for fast tokens)
#pragma unroll
        for (int h = 0; h < TPT; h++) {
            const float sg = __fmaf_rn(-2.0f, dm[h], xs[h]);
            if (sg < m[h]) { m[h] = sg; gsel[h] = g; }   // strict <: earliest group wins
        }
    }

#pragma unroll
    for (int h = 0; h < TPT; h++) {
        const int n = tokbase + h * TPB + tid;
        const unsigned long long key =
            (((unsigned long long)ford(m[h])) << 32) | (unsigned)(blockIdx.y * NGROUP + gsel[h]);
        atomicMin(&g_best[n], key);
    }
}

// ---------- kernel 3: recover first index in winning group (fast tokens) ----------
// Half-warp per token: 16 lanes evaluate the group's codes; ballot picks first exact match.
__global__ void vq_final(const float* __restrict__ hs,
                         const float4* __restrict__ emb,
                         float* __restrict__ out) {
    const int lane = threadIdx.x & 31;
    const int half = lane >> 4;
    const int u    = lane & 15;
    const int n    = (blockIdx.x * blockDim.x + threadIdx.x) >> 4;
    if (n >= NTOK) return;

    const unsigned long long key = g_best[n];
    const unsigned int grp    = (unsigned int)(key & 0xFFFFFFFFull);
    const unsigned int m_bits = ((unsigned int)(key >> 32)) & 0x7FFFFFFFu;
    const int kbase = (int)grp * GROUP;

    const int t = n / CH_STRIDE, hw = n % CH_STRIDE;
    float x0, x1, x2, x3;
    const float xsv = token_xs(hs + t * T_STRIDE + hw, x0, x1, x2, x3);

    const float s = exact_score(x0, x1, x2, x3, xsv, __ldg(&emb[kbase + u]));

    const unsigned int bal = __ballot_sync(0xFFFFFFFFu, __float_as_uint(s) == m_bits);
    if (u == 0) {
        const unsigned int mybits = half ? (bal >> 16) : (bal & 0xFFFFu);
        const int first = mybits ? (__ffs(mybits) - 1) : 0;   // fallback: group base
        out[n] = (float)(kbase + first);
    }
}

// ---------- kernel 4: exact full rescan for slow tokens (xs < 0.125) ----------
__global__ void __launch_bounds__(256) vq_fix(const float* __restrict__ hs,
                                              const float4* __restrict__ emb,
                                              float* __restrict__ out) {
    __shared__ unsigned long long red[256];
    for (int n = blockIdx.x; n < NTOK; n += FIXBLKS) {
        if (!g_slow[n]) continue;
        const int t = n / CH_STRIDE, hw = n % CH_STRIDE;
        float x0, x1, x2, x3;
        const float xsv = token_xs(hs + t * T_STRIDE + hw, x0, x1, x2, x3);

        unsigned long long best = ~0ull;
        for (int k = threadIdx.x; k < CODEBOOK; k += 256) {
            const float s = exact_score(x0, x1, x2, x3, xsv, __ldg(&emb[k]));
            const unsigned long long key = (((unsigned long long)ford(s)) << 32) | (unsigned)k;
            best = (key < best) ? key : best;
        }
        red[threadIdx.x] = best;
        __syncthreads();
        for (int off = 128; off > 0; off >>= 1) {
            if (threadIdx.x < off && red[threadIdx.x + off] < red[threadIdx.x])
                red[threadIdx.x] = red[threadIdx.x + off];
            __syncthreads();
        }
        if (threadIdx.x == 0)
            out[n] = (float)(unsigned int)(red[0] & 0xFFFFFFFFull);
        __syncthreads();
    }
}

extern "C" void kernel_launch(void* const* d_in, const int* in_sizes, int n_in,
                              void* d_out, int out_size) {
    // Resolve input order by element count: hidden_state 36864, embedding 131072
    const float*  hs;
    const float4* emb;
    if (in_sizes[0] == NTOK * 4) {
        hs  = (const float*)d_in[0];
        emb = (const float4*)d_in[1];
    } else {
        emb = (const float4*)d_in[0];
        hs  = (const float*)d_in[1];
    }
    float* out = (float*)d_out;

    vq_prep<<<CODEBOOK / 256, 256>>>(emb, hs);
    vq_main<<<dim3(TOKBLKS, CHUNKS, 1), TPB>>>(hs);
    vq_final<<<(NTOK * 16 + 255) / 256, 256>>>(hs, emb, out);
    vq_fix<<<FIXBLKS, 256>>>(hs, emb, out);
}

// round 7
// speedup vs baseline: 1.4348x; 1.4348x over previous
#include <cuda_runtime.h>
#include <cstdint>

#define CODEBOOK 32768
#define NTOK     9216      // 1*4*48*48 tokens
#define CH_STRIDE 2304     // 48*48
#define T_STRIDE  9216     // 4 channels * 2304

#define TPB     128
#define TPT     4                           // tokens per thread (2 f32x2 pairs)
#define CHUNKS  64
#define CHUNK   (CODEBOOK / CHUNKS)         // 512 codes per chunk
#define GROUP   16
#define NGROUP  (CHUNK / GROUP)             // 32 groups per chunk
#define TOKBLKS (NTOK / (TPB * TPT))        // 18 token blocks

// Scratch (static __device__ — no allocation)
__device__ ulonglong2          g_pkA[CODEBOOK];   // (e0,e0) (e1,e1) packed f32x2
__device__ ulonglong2          g_pkB[CODEBOOK];   // (e2,e2) (e3,e3)
__device__ unsigned long long  g_best[NTOK];      // (ford(s_g) << 32) | global_group_id
__device__ unsigned int        g_slow[NTOK];      // 1 if xs < 0.125 (needs exact t per code)

// ---------- packed f32x2 helpers ----------
static __device__ __forceinline__ unsigned long long pack2(float lo, float hi) {
    unsigned long long r;
    asm("mov.b64 %0,{%1,%2};" : "=l"(r) : "f"(lo), "f"(hi));
    return r;
}
static __device__ __forceinline__ unsigned long long mul2(unsigned long long a, unsigned long long b) {
    unsigned long long d;
    asm("mul.rn.f32x2 %0,%1,%2;" : "=l"(d) : "l"(a), "l"(b));
    return d;
}
static __device__ __forceinline__ unsigned long long add2(unsigned long long a, unsigned long long b) {
    unsigned long long d;
    asm("add.rn.f32x2 %0,%1,%2;" : "=l"(d) : "l"(a), "l"(b));
    return d;
}
// lo/hi = a + b per half, unpacked to scalars
static __device__ __forceinline__ void add2_unpack(unsigned long long a, unsigned long long b,
                                                   float& lo, float& hi) {
    asm("{\n\t"
        ".reg .b64 t;\n\t"
        "add.rn.f32x2 t,%2,%3;\n\t"
        "mov.b64 {%0,%1},t;\n\t"
        "}" : "=f"(lo), "=f"(hi) : "l"(a), "l"(b));
}

// scores are positive finite; ford is monotone there
static __device__ __forceinline__ unsigned int ford(float v) {
    return __float_as_uint(v) | 0x80000000u;
}

static __device__ __forceinline__ float token_xs(const float* p, float& x0, float& x1,
                                                 float& x2, float& x3) {
    x0 = __ldg(p); x1 = __ldg(p + CH_STRIDE);
    x2 = __ldg(p + 2 * CH_STRIDE); x3 = __ldg(p + 3 * CH_STRIDE);
    return __fadd_rn(__fadd_rn(__fadd_rn(__fmul_rn(x0, x0), __fmul_rn(x1, x1)),
                               __fmul_rn(x2, x2)), __fmul_rn(x3, x3));
}

// exact reference score: s = fl(fl(xs+e2) - 2*fl_leftassoc_dot)
static __device__ __forceinline__ float exact_score(float x0, float x1, float x2, float x3,
                                                    float xs, float4 e) {
    const float e2 = __fadd_rn(__fadd_rn(__fadd_rn(__fmul_rn(e.x, e.x), __fmul_rn(e.y, e.y)),
                                         __fmul_rn(e.z, e.z)), __fmul_rn(e.w, e.w));
    const float dot = __fadd_rn(__fadd_rn(__fadd_rn(__fmul_rn(x0, e.x), __fmul_rn(x1, e.y)),
                                          __fmul_rn(x2, e.z)), __fmul_rn(x3, e.w));
    return __fmaf_rn(-2.0f, dot, __fadd_rn(xs, e2));
}

// ---------- kernel 1: codebook transform + scratch init + slow-token flags ----------
__global__ void vq_prep(const float4* __restrict__ emb, const float* __restrict__ hs) {
    int k = blockIdx.x * blockDim.x + threadIdx.x;
    if (k < NTOK) {
        g_best[k] = ~0ull;
        const int t = k / CH_STRIDE, hw = k % CH_STRIDE;
        float x0, x1, x2, x3;
        const float xs = token_xs(hs + t * T_STRIDE + hw, x0, x1, x2, x3);
        // xs >= 0.125 guarantees fl(xs + e2) == xs for all codes (e2 <= 2^-28 < ulp/2)
        g_slow[k] = (xs < 0.125f) ? 1u : 0u;
    }
    if (k < CODEBOOK) {
        float4 e = __ldg(&emb[k]);
        g_pkA[k] = make_ulonglong2(pack2(e.x, e.x), pack2(e.y, e.y));
        g_pkB[k] = make_ulonglong2(pack2(e.z, e.z), pack2(e.w, e.w));
    }
}

// ---------- kernel 2: main scan (dot-max per group; score once per group) ----------
// blockIdx.x : token group (512 tokens, 4/thread), blockIdx.y : codebook chunk (512 codes)
__global__ void __launch_bounds__(TPB) vq_main(const float* __restrict__ hs) {
    const int tid     = threadIdx.x;
    const int tokbase = blockIdx.x * (TPB * TPT);
    const int base    = blockIdx.y * CHUNK;

    float x[4][TPT], xs[TPT];
#pragma unroll
    for (int h = 0; h < TPT; h++) {
        const int n = tokbase + h * TPB + tid;
        const int t = n / CH_STRIDE, hw = n % CH_STRIDE;
        xs[h] = token_xs(hs + t * T_STRIDE + hw, x[0][h], x[1][h], x[2][h], x[3][h]);
    }

    unsigned long long X0[2], X1[2], X2[2], X3[2];
#pragma unroll
    for (int p2 = 0; p2 < 2; p2++) {
        X0[p2] = pack2(x[0][2 * p2], x[0][2 * p2 + 1]);
        X1[p2] = pack2(x[1][2 * p2], x[1][2 * p2 + 1]);
        X2[p2] = pack2(x[2][2 * p2], x[2][2 * p2 + 1]);
        X3[p2] = pack2(x[3][2 * p2], x[3][2 * p2 + 1]);
    }
    const float INF = __int_as_float(0x7f800000);
    const float NINF = __int_as_float(0xff800000);

    float m[TPT]    = {INF, INF, INF, INF};   // running min group-score
    int   gsel[TPT] = {0, 0, 0, 0};           // earliest group achieving it

    for (int g = 0; g < NGROUP; g++) {
        float dm[TPT] = {NINF, NINF, NINF, NINF};   // group dot max per token
#pragma unroll
        for (int u = 0; u < GROUP; u++) {
            const int k = base + g * GROUP + u;
            const ulonglong2 A = g_pkA[k];
            const ulonglong2 B = g_pkB[k];
#pragma unroll
            for (int p2 = 0; p2 < 2; p2++) {
                // dot = ((x0*e0 + x1*e1) + x2*e2) + x3*e3, per-half rn (matches reference)
                unsigned long long d = add2(mul2(X0[p2], A.x), mul2(X1[p2], A.y));
                d = add2(d, mul2(X2[p2], B.x));
                float d0, d1;
                add2_unpack(d, mul2(X3[p2], B.y), d0, d1);
                dm[2 * p2]     = fmaxf(dm[2 * p2], d0);
                dm[2 * p2 + 1] = fmaxf(dm[2 * p2 + 1], d1);
            }
        }
        // group min score = fl(xs - 2*dmax) (monotone; exact for fast tokens)
#pragma unroll
        for (int h = 0; h < TPT; h++) {
            const float sg = __fmaf_rn(-2.0f, dm[h], xs[h]);
            if (sg < m[h]) { m[h] = sg; gsel[h] = g; }   // strict <: earliest group wins
        }
    }

#pragma unroll
    for (int h = 0; h < TPT; h++) {
        const int n = tokbase + h * TPB + tid;
        const unsigned long long key =
            (((unsigned long long)ford(m[h])) << 32) | (unsigned)(blockIdx.y * NGROUP + gsel[h]);
        atomicMin(&g_best[n], key);
    }
}

// ---------- kernel 3: recover first index in winning group (fast tokens) ----------
// Half-warp per token: 16 lanes evaluate the group's codes; ballot picks first exact match.
__global__ void vq_final(const float* __restrict__ hs,
                         const float4* __restrict__ emb,
                         float* __restrict__ out) {
    const int lane = threadIdx.x & 31;
    const int half = lane >> 4;
    const int u    = lane & 15;
    const int n    = (blockIdx.x * blockDim.x + threadIdx.x) >> 4;
    if (n >= NTOK) return;

    const unsigned long long key = g_best[n];
    const unsigned int grp    = (unsigned int)(key & 0xFFFFFFFFull);
    const unsigned int m_bits = ((unsigned int)(key >> 32)) & 0x7FFFFFFFu;
    const int kbase = (int)grp * GROUP;

    const int t = n / CH_STRIDE, hw = n % CH_STRIDE;
    float x0, x1, x2, x3;
    const float xsv = token_xs(hs + t * T_STRIDE + hw, x0, x1, x2, x3);

    const float s = exact_score(x0, x1, x2, x3, xsv, __ldg(&emb[kbase + u]));

    const unsigned int bal = __ballot_sync(0xFFFFFFFFu, __float_as_uint(s) == m_bits);
    if (u == 0) {
        const unsigned int mybits = half ? (bal >> 16) : (bal & 0xFFFFu);
        const int first = mybits ? (__ffs(mybits) - 1) : 0;   // fallback: group base
        out[n] = (float)(kbase + first);
    }
}

// ---------- kernel 4: exact full rescan for slow tokens (xs < 0.125) ----------
// 36 blocks; block b ballot-collects slow tokens among [b*256, b*256+256), then
// does a full-block 32768-code exact scan per listed token. Most blocks exit fast.
__global__ void __launch_bounds__(256) vq_fix(const float* __restrict__ hs,
                                              const float4* __restrict__ emb,
                                              float* __restrict__ out) {
    __shared__ unsigned long long red[256];
    __shared__ int s_list[256];
    __shared__ int s_cnt;

    if (threadIdx.x == 0) s_cnt = 0;
    __syncthreads();

    const int n0 = blockIdx.x * 256 + threadIdx.x;
    if (n0 < NTOK && g_slow[n0]) {
        const int p = atomicAdd(&s_cnt, 1);
        s_list[p] = n0;
    }
    __syncthreads();

    const int cnt = s_cnt;
    for (int i = 0; i < cnt; i++) {
        const int n = s_list[i];
        const int t = n / CH_STRIDE, hw = n % CH_STRIDE;
        float x0, x1, x2, x3;
        const float xsv = token_xs(hs + t * T_STRIDE + hw, x0, x1, x2, x3);

        unsigned long long best = ~0ull;
#pragma unroll 4
        for (int k = threadIdx.x; k < CODEBOOK; k += 256) {
            const float s = exact_score(x0, x1, x2, x3, xsv, __ldg(&emb[k]));
            const unsigned long long key = (((unsigned long long)ford(s)) << 32) | (unsigned)k;
            best = (key < best) ? key : best;
        }
        red[threadIdx.x] = best;
        __syncthreads();
        for (int off = 128; off > 0; off >>= 1) {
            if (threadIdx.x < off && red[threadIdx.x + off] < red[threadIdx.x])
                red[threadIdx.x] = red[threadIdx.x + off];
            __syncthreads();
        }
        if (threadIdx.x == 0)
            out[n] = (float)(unsigned int)(red[0] & 0xFFFFFFFFull);
        __syncthreads();
    }
}

extern "C" void kernel_launch(void* const* d_in, const int* in_sizes, int n_in,
                              void* d_out, int out_size) {
    // Resolve input order by element count: hidden_state 36864, embedding 131072
    const float*  hs;
    const float4* emb;
    if (in_sizes[0] == NTOK * 4) {
        hs  = (const float*)d_in[0];
        emb = (const float4*)d_in[1];
    } else {
        emb = (const float4*)d_in[0];
        hs  = (const float*)d_in[1];
    }
    float* out = (float*)d_out;

    vq_prep<<<CODEBOOK / 256, 256>>>(emb, hs);
    vq_main<<<dim3(TOKBLKS, CHUNKS, 1), TPB>>>(hs);
    vq_final<<<(NTOK * 16 + 255) / 256, 256>>>(hs, emb, out);
    vq_fix<<<(NTOK + 255) / 256, 256>>>(hs, emb, out);
}

// round 8
// speedup vs baseline: 1.8068x; 1.2593x over previous
#include <cuda_runtime.h>
#include <cstdint>

#define CODEBOOK 32768
#define NTOK     9216      // 1*4*48*48 tokens
#define CH_STRIDE 2304     // 48*48
#define T_STRIDE  9216     // 4 channels * 2304

#define TPB     128
#define TPT     4                           // tokens per thread (2 f32x2 pairs)
#define CHUNKS  64
#define CHUNK   (CODEBOOK / CHUNKS)         // 512 codes per chunk
#define GROUP   16
#define NGROUP  (CHUNK / GROUP)             // 32 groups per chunk
#define TOKBLKS (NTOK / (TPB * TPT))        // 18 token blocks
#define FIXSEG  16                          // codebook segments for the fix pass
#define SEGLEN  (CODEBOOK / FIXSEG)         // 2048 codes per segment
#define NTILES  ((NTOK + 255) / 256)        // 36 token tiles

// Scratch (static __device__ — no allocation)
__device__ ulonglong2          g_pkA[CODEBOOK];   // (e0,e0) (e1,e1) packed f32x2
__device__ ulonglong2          g_pkB[CODEBOOK];   // (e2,e2) (e3,e3)
__device__ unsigned long long  g_best[NTOK];      // (ford(s_g) << 32) | global_group_id
__device__ unsigned long long  g_fixbest[NTOK];   // exact (ford_s(s) << 32) | k for slow tokens
__device__ unsigned int        g_slow[NTOK];      // 1 if xs < 0.125

// ---------- packed f32x2 helpers ----------
static __device__ __forceinline__ unsigned long long pack2(float lo, float hi) {
    unsigned long long r;
    asm("mov.b64 %0,{%1,%2};" : "=l"(r) : "f"(lo), "f"(hi));
    return r;
}
static __device__ __forceinline__ unsigned long long mul2(unsigned long long a, unsigned long long b) {
    unsigned long long d;
    asm("mul.rn.f32x2 %0,%1,%2;" : "=l"(d) : "l"(a), "l"(b));
    return d;
}
static __device__ __forceinline__ unsigned long long add2(unsigned long long a, unsigned long long b) {
    unsigned long long d;
    asm("add.rn.f32x2 %0,%1,%2;" : "=l"(d) : "l"(a), "l"(b));
    return d;
}
static __device__ __forceinline__ void add2_unpack(unsigned long long a, unsigned long long b,
                                                   float& lo, float& hi) {
    asm("{\n\t"
        ".reg .b64 t;\n\t"
        "add.rn.f32x2 t,%2,%3;\n\t"
        "mov.b64 {%0,%1},t;\n\t"
        "}" : "=f"(lo), "=f"(hi) : "l"(a), "l"(b));
}

// main-path scores are provably positive (xs >= 0.125, |2dot| < 1e-4)
static __device__ __forceinline__ unsigned int ford(float v) {
    return __float_as_uint(v) | 0x80000000u;
}
// sign-safe total order (slow path: s could round slightly negative)
static __device__ __forceinline__ unsigned int ford_s(float v) {
    unsigned int b = __float_as_uint(v);
    return (b & 0x80000000u) ? ~b : (b | 0x80000000u);
}

static __device__ __forceinline__ float token_xs(const float* p, float& x0, float& x1,
                                                 float& x2, float& x3) {
    x0 = __ldg(p); x1 = __ldg(p + CH_STRIDE);
    x2 = __ldg(p + 2 * CH_STRIDE); x3 = __ldg(p + 3 * CH_STRIDE);
    return __fadd_rn(__fadd_rn(__fadd_rn(__fmul_rn(x0, x0), __fmul_rn(x1, x1)),
                               __fmul_rn(x2, x2)), __fmul_rn(x3, x3));
}

// exact reference score: s = fl(fl(xs+e2) - 2*fl_leftassoc_dot)
static __device__ __forceinline__ float exact_score(float x0, float x1, float x2, float x3,
                                                    float xs, float4 e) {
    const float e2 = __fadd_rn(__fadd_rn(__fadd_rn(__fmul_rn(e.x, e.x), __fmul_rn(e.y, e.y)),
                                         __fmul_rn(e.z, e.z)), __fmul_rn(e.w, e.w));
    const float dot = __fadd_rn(__fadd_rn(__fadd_rn(__fmul_rn(x0, e.x), __fmul_rn(x1, e.y)),
                                          __fmul_rn(x2, e.z)), __fmul_rn(x3, e.w));
    return __fmaf_rn(-2.0f, dot, __fadd_rn(xs, e2));
}

// ---------- kernel 1: codebook transform + scratch init + slow-token flags ----------
__global__ void vq_prep(const float4* __restrict__ emb, const float* __restrict__ hs) {
    int k = blockIdx.x * blockDim.x + threadIdx.x;
    if (k < NTOK) {
        g_best[k]    = ~0ull;
        g_fixbest[k] = ~0ull;
        const int t = k / CH_STRIDE, hw = k % CH_STRIDE;
        float x0, x1, x2, x3;
        const float xs = token_xs(hs + t * T_STRIDE + hw, x0, x1, x2, x3);
        // xs >= 0.125 guarantees fl(xs + e2) == xs for all codes (e2 <= 2^-28 < ulp/2)
        g_slow[k] = (xs < 0.125f) ? 1u : 0u;
    }
    if (k < CODEBOOK) {
        float4 e = __ldg(&emb[k]);
        g_pkA[k] = make_ulonglong2(pack2(e.x, e.x), pack2(e.y, e.y));
        g_pkB[k] = make_ulonglong2(pack2(e.z, e.z), pack2(e.w, e.w));
    }
}

// ---------- kernel 2: main scan (dot-max per group; score once per group) ----------
__global__ void __launch_bounds__(TPB) vq_main(const float* __restrict__ hs) {
    const int tid     = threadIdx.x;
    const int tokbase = blockIdx.x * (TPB * TPT);
    const int base    = blockIdx.y * CHUNK;

    float x[4][TPT], xs[TPT];
#pragma unroll
    for (int h = 0; h < TPT; h++) {
        const int n = tokbase + h * TPB + tid;
        const int t = n / CH_STRIDE, hw = n % CH_STRIDE;
        xs[h] = token_xs(hs + t * T_STRIDE + hw, x[0][h], x[1][h], x[2][h], x[3][h]);
    }

    unsigned long long X0[2], X1[2], X2[2], X3[2];
#pragma unroll
    for (int p2 = 0; p2 < 2; p2++) {
        X0[p2] = pack2(x[0][2 * p2], x[0][2 * p2 + 1]);
        X1[p2] = pack2(x[1][2 * p2], x[1][2 * p2 + 1]);
        X2[p2] = pack2(x[2][2 * p2], x[2][2 * p2 + 1]);
        X3[p2] = pack2(x[3][2 * p2], x[3][2 * p2 + 1]);
    }
    const float INF = __int_as_float(0x7f800000);
    const float NINF = __int_as_float(0xff800000);

    float m[TPT]    = {INF, INF, INF, INF};
    int   gsel[TPT] = {0, 0, 0, 0};

    for (int g = 0; g < NGROUP; g++) {
        float dm[TPT] = {NINF, NINF, NINF, NINF};
#pragma unroll
        for (int u = 0; u < GROUP; u++) {
            const int k = base + g * GROUP + u;
            const ulonglong2 A = g_pkA[k];
            const ulonglong2 B = g_pkB[k];
#pragma unroll
            for (int p2 = 0; p2 < 2; p2++) {
                // dot = ((x0*e0 + x1*e1) + x2*e2) + x3*e3, per-half rn (matches reference)
                unsigned long long d = add2(mul2(X0[p2], A.x), mul2(X1[p2], A.y));
                d = add2(d, mul2(X2[p2], B.x));
                float d0, d1;
                add2_unpack(d, mul2(X3[p2], B.y), d0, d1);
                dm[2 * p2]     = fmaxf(dm[2 * p2], d0);
                dm[2 * p2 + 1] = fmaxf(dm[2 * p2 + 1], d1);
            }
        }
#pragma unroll
        for (int h = 0; h < TPT; h++) {
            const float sg = __fmaf_rn(-2.0f, dm[h], xs[h]);   // exact for fast tokens
            if (sg < m[h]) { m[h] = sg; gsel[h] = g; }         // strict <: earliest group
        }
    }

#pragma unroll
    for (int h = 0; h < TPT; h++) {
        const int n = tokbase + h * TPB + tid;
        const unsigned long long key =
            (((unsigned long long)ford(m[h])) << 32) | (unsigned)(blockIdx.y * NGROUP + gsel[h]);
        atomicMin(&g_best[n], key);
    }
}

// ---------- kernel 3: exact rescan for slow tokens, tile x segment parallel ----------
// Block (tile, seg): collect slow tokens in tile of 256; scan 2048-code segment each.
__global__ void __launch_bounds__(256) vq_fix(const float* __restrict__ hs,
                                              const float4* __restrict__ emb) {
    __shared__ unsigned long long red[256];
    __shared__ int s_list[256];
    __shared__ int s_cnt;

    if (threadIdx.x == 0) s_cnt = 0;
    __syncthreads();

    const int n0 = blockIdx.x * 256 + threadIdx.x;
    if (n0 < NTOK && g_slow[n0]) {
        const int p = atomicAdd(&s_cnt, 1);
        s_list[p] = n0;
    }
    __syncthreads();

    const int cnt = s_cnt;
    if (cnt == 0) return;
    const int kbase = blockIdx.y * SEGLEN;

    for (int i = 0; i < cnt; i++) {
        const int n = s_list[i];
        const int t = n / CH_STRIDE, hw = n % CH_STRIDE;
        float x0, x1, x2, x3;
        const float xsv = token_xs(hs + t * T_STRIDE + hw, x0, x1, x2, x3);

        unsigned long long best = ~0ull;
#pragma unroll 4
        for (int k = kbase + threadIdx.x; k < kbase + SEGLEN; k += 256) {
            const float s = exact_score(x0, x1, x2, x3, xsv, __ldg(&emb[k]));
            const unsigned long long key = (((unsigned long long)ford_s(s)) << 32) | (unsigned)k;
            best = (key < best) ? key : best;
        }
        red[threadIdx.x] = best;
        __syncthreads();
        for (int off = 128; off > 0; off >>= 1) {
            if (threadIdx.x < off && red[threadIdx.x + off] < red[threadIdx.x])
                red[threadIdx.x] = red[threadIdx.x + off];
            __syncthreads();
        }
        if (threadIdx.x == 0)
            atomicMin(&g_fixbest[n], red[0]);
        __syncthreads();
    }
}

// ---------- kernel 4: recover first index (fast) / pick fix result (slow) ----------
__global__ void vq_final(const float* __restrict__ hs,
                         const float4* __restrict__ emb,
                         float* __restrict__ out) {
    const int lane = threadIdx.x & 31;
    const int half = lane >> 4;
    const int u    = lane & 15;
    const int n    = (blockIdx.x * blockDim.x + threadIdx.x) >> 4;
    if (n >= NTOK) return;

    const unsigned long long key = g_best[n];
    const unsigned int grp    = (unsigned int)(key & 0xFFFFFFFFull);
    const unsigned int m_bits = ((unsigned int)(key >> 32)) & 0x7FFFFFFFu;
    const int kbase = (int)grp * GROUP;

    const int t = n / CH_STRIDE, hw = n % CH_STRIDE;
    float x0, x1, x2, x3;
    const float xsv = token_xs(hs + t * T_STRIDE + hw, x0, x1, x2, x3);

    const float s = exact_score(x0, x1, x2, x3, xsv, __ldg(&emb[kbase + u]));

    // all 32 lanes participate (two tokens per warp)
    const unsigned int bal = __ballot_sync(0xFFFFFFFFu, __float_as_uint(s) == m_bits);
    if (u == 0) {
        const unsigned int mybits = half ? (bal >> 16) : (bal & 0xFFFFu);
        const int first = mybits ? (__ffs(mybits) - 1) : 0;
        const float fast_idx = (float)(kbase + first);
        const float slow_idx = (float)(unsigned int)(g_fixbest[n] & 0xFFFFFFFFull);
        out[n] = g_slow[n] ? slow_idx : fast_idx;
    }
}

extern "C" void kernel_launch(void* const* d_in, const int* in_sizes, int n_in,
                              void* d_out, int out_size) {
    // Resolve input order by element count: hidden_state 36864, embedding 131072
    const float*  hs;
    const float4* emb;
    if (in_sizes[0] == NTOK * 4) {
        hs  = (const float*)d_in[0];
        emb = (const float4*)d_in[1];
    } else {
        emb = (const float4*)d_in[0];
        hs  = (const float*)d_in[1];
    }
    float* out = (float*)d_out;

    vq_prep<<<CODEBOOK / 256, 256>>>(emb, hs);
    vq_main<<<dim3(TOKBLKS, CHUNKS, 1), TPB>>>(hs);
    vq_fix<<<dim3(NTILES, FIXSEG, 1), 256>>>(hs, emb);
    vq_final<<<(NTOK * 16 + 255) / 256, 256>>>(hs, emb, out);
}

// round 9
// speedup vs baseline: 1.8283x; 1.0119x over previous
#include <cuda_runtime.h>
#include <cstdint>

#define CODEBOOK 32768
#define NTOK     9216      // 1*4*48*48 tokens
#define CH_STRIDE 2304     // 48*48
#define T_STRIDE  9216     // 4 channels * 2304

#define TPB     128
#define TPT     8                           // tokens per thread (4 f32x2 pairs)
#define NPAIR   (TPT / 2)
#define CHUNKS  64
#define CHUNK   (CODEBOOK / CHUNKS)         // 512 codes per chunk
#define GROUP   16
#define NGROUP  (CHUNK / GROUP)             // 32 groups per chunk
#define TOKBLKS (NTOK / (TPB * TPT))        // 9 token blocks
#define FIXSEG  16                          // codebook segments for the fix pass
#define SEGLEN  (CODEBOOK / FIXSEG)         // 2048 codes per segment
#define NTILES  ((NTOK + 255) / 256)        // 36 token tiles

// Scratch (static __device__ — no allocation)
__device__ ulonglong2          g_pkA[CODEBOOK];   // (e0,e0) (e1,e1) packed f32x2
__device__ ulonglong2          g_pkB[CODEBOOK];   // (e2,e2) (e3,e3)
__device__ unsigned long long  g_best[NTOK];      // (ford(s_g) << 32) | global_group_id
__device__ unsigned long long  g_fixbest[NTOK];   // exact (ford_s(s) << 32) | k for slow tokens
__device__ unsigned int        g_slow[NTOK];      // 1 if xs < 0.125

// ---------- packed f32x2 helpers ----------
static __device__ __forceinline__ unsigned long long pack2(float lo, float hi) {
    unsigned long long r;
    asm("mov.b64 %0,{%1,%2};" : "=l"(r) : "f"(lo), "f"(hi));
    return r;
}
static __device__ __forceinline__ unsigned long long mul2(unsigned long long a, unsigned long long b) {
    unsigned long long d;
    asm("mul.rn.f32x2 %0,%1,%2;" : "=l"(d) : "l"(a), "l"(b));
    return d;
}
static __device__ __forceinline__ unsigned long long fma2(unsigned long long a, unsigned long long b,
                                                          unsigned long long c) {
    unsigned long long d;
    asm("fma.rn.f32x2 %0,%1,%2,%3;" : "=l"(d) : "l"(a), "l"(b), "l"(c));
    return d;
}
static __device__ __forceinline__ void unpack2(unsigned long long v, float& lo, float& hi) {
    asm("mov.b64 {%0,%1},%2;" : "=f"(lo), "=f"(hi) : "l"(v));
}

// main-path scores are provably positive (xs >= 0.125, |2dot| < 1e-4)
static __device__ __forceinline__ unsigned int ford(float v) {
    return __float_as_uint(v) | 0x80000000u;
}
// sign-safe total order
static __device__ __forceinline__ unsigned int ford_s(float v) {
    unsigned int b = __float_as_uint(v);
    return (b & 0x80000000u) ? ~b : (b | 0x80000000u);
}

static __device__ __forceinline__ float token_xs(const float* p, float& x0, float& x1,
                                                 float& x2, float& x3) {
    x0 = __ldg(p); x1 = __ldg(p + CH_STRIDE);
    x2 = __ldg(p + 2 * CH_STRIDE); x3 = __ldg(p + 3 * CH_STRIDE);
    return __fadd_rn(__fadd_rn(__fadd_rn(__fmul_rn(x0, x0), __fmul_rn(x1, x1)),
                               __fmul_rn(x2, x2)), __fmul_rn(x3, x3));
}

// exact reference score: s = fl(fl(xs+e2) - 2*fl_leftassoc_dot)
static __device__ __forceinline__ float exact_score(float x0, float x1, float x2, float x3,
                                                    float xs, float4 e) {
    const float e2 = __fadd_rn(__fadd_rn(__fadd_rn(__fmul_rn(e.x, e.x), __fmul_rn(e.y, e.y)),
                                         __fmul_rn(e.z, e.z)), __fmul_rn(e.w, e.w));
    const float dot = __fadd_rn(__fadd_rn(__fadd_rn(__fmul_rn(x0, e.x), __fmul_rn(x1, e.y)),
                                          __fmul_rn(x2, e.z)), __fmul_rn(x3, e.w));
    return __fmaf_rn(-2.0f, dot, __fadd_rn(xs, e2));
}

// ---------- kernel 1: codebook transform + scratch init + slow-token flags ----------
__global__ void vq_prep(const float4* __restrict__ emb, const float* __restrict__ hs) {
    int k = blockIdx.x * blockDim.x + threadIdx.x;
    if (k < NTOK) {
        g_best[k]    = ~0ull;
        g_fixbest[k] = ~0ull;
        const int t = k / CH_STRIDE, hw = k % CH_STRIDE;
        float x0, x1, x2, x3;
        const float xs = token_xs(hs + t * T_STRIDE + hw, x0, x1, x2, x3);
        // xs >= 0.125 guarantees fl(xs + e2) == xs for all codes (e2 <= 2^-28 < ulp/2)
        g_slow[k] = (xs < 0.125f) ? 1u : 0u;
    }
    if (k < CODEBOOK) {
        float4 e = __ldg(&emb[k]);
        g_pkA[k] = make_ulonglong2(pack2(e.x, e.x), pack2(e.y, e.y));
        g_pkB[k] = make_ulonglong2(pack2(e.z, e.z), pack2(e.w, e.w));
    }
}

// ---------- kernel 2: main scan (FMA-chain dot; dot-max per group) ----------
// blockIdx.x : token group (1024 tokens, 8/thread), blockIdx.y : codebook chunk (512 codes)
__global__ void __launch_bounds__(TPB) vq_main(const float* __restrict__ hs) {
    const int tid     = threadIdx.x;
    const int tokbase = blockIdx.x * (TPB * TPT);
    const int base    = blockIdx.y * CHUNK;

    float xs[TPT];
    unsigned long long X0[NPAIR], X1[NPAIR], X2[NPAIR], X3[NPAIR];
#pragma unroll
    for (int p2 = 0; p2 < NPAIR; p2++) {
        float a0, a1, a2, a3, b0, b1, b2, b3;
        {
            const int n = tokbase + (2 * p2) * TPB + tid;
            const int t = n / CH_STRIDE, hw = n % CH_STRIDE;
            xs[2 * p2] = token_xs(hs + t * T_STRIDE + hw, a0, a1, a2, a3);
        }
        {
            const int n = tokbase + (2 * p2 + 1) * TPB + tid;
            const int t = n / CH_STRIDE, hw = n % CH_STRIDE;
            xs[2 * p2 + 1] = token_xs(hs + t * T_STRIDE + hw, b0, b1, b2, b3);
        }
        X0[p2] = pack2(a0, b0); X1[p2] = pack2(a1, b1);
        X2[p2] = pack2(a2, b2); X3[p2] = pack2(a3, b3);
    }

    const float INF  = __int_as_float(0x7f800000);
    const float NINF = __int_as_float(0xff800000);

    float m[TPT];
    int   gsel[TPT];
#pragma unroll
    for (int h = 0; h < TPT; h++) { m[h] = INF; gsel[h] = 0; }

    for (int g = 0; g < NGROUP; g++) {
        float dm[TPT];
#pragma unroll
        for (int h = 0; h < TPT; h++) dm[h] = NINF;
#pragma unroll
        for (int u = 0; u < GROUP; u++) {
            const int k = base + g * GROUP + u;
            const ulonglong2 A = g_pkA[k];
            const ulonglong2 B = g_pkB[k];
#pragma unroll
            for (int p2 = 0; p2 < NPAIR; p2++) {
                // FMA-chain dot (4 packed ops). Differs from reference rounding by
                // ~1e-11 << score ulp 4.8e-7; exact argmin recovered in vq_final.
                unsigned long long d = mul2(X0[p2], A.x);
                d = fma2(X1[p2], A.y, d);
                d = fma2(X2[p2], B.x, d);
                d = fma2(X3[p2], B.y, d);
                float d0, d1;
                unpack2(d, d0, d1);
                dm[2 * p2]     = fmaxf(dm[2 * p2], d0);
                dm[2 * p2 + 1] = fmaxf(dm[2 * p2 + 1], d1);
            }
        }
#pragma unroll
        for (int h = 0; h < TPT; h++) {
            const float sg = __fmaf_rn(-2.0f, dm[h], xs[h]);   // group min score (monotone)
            if (sg < m[h]) { m[h] = sg; gsel[h] = g; }         // strict <: earliest group
        }
    }

#pragma unroll
    for (int h = 0; h < TPT; h++) {
        const int n = tokbase + h * TPB + tid;
        const unsigned long long key =
            (((unsigned long long)ford(m[h])) << 32) | (unsigned)(blockIdx.y * NGROUP + gsel[h]);
        atomicMin(&g_best[n], key);
    }
}

// ---------- kernel 3: exact rescan for slow tokens, tile x segment parallel ----------
__global__ void __launch_bounds__(256) vq_fix(const float* __restrict__ hs,
                                              const float4* __restrict__ emb) {
    __shared__ unsigned long long red[256];
    __shared__ int s_list[256];
    __shared__ int s_cnt;

    if (threadIdx.x == 0) s_cnt = 0;
    __syncthreads();

    const int n0 = blockIdx.x * 256 + threadIdx.x;
    if (n0 < NTOK && g_slow[n0]) {
        const int p = atomicAdd(&s_cnt, 1);
        s_list[p] = n0;
    }
    __syncthreads();

    const int cnt = s_cnt;
    if (cnt == 0) return;
    const int kbase = blockIdx.y * SEGLEN;

    for (int i = 0; i < cnt; i++) {
        const int n = s_list[i];
        const int t = n / CH_STRIDE, hw = n % CH_STRIDE;
        float x0, x1, x2, x3;
        const float xsv = token_xs(hs + t * T_STRIDE + hw, x0, x1, x2, x3);

        unsigned long long best = ~0ull;
#pragma unroll 4
        for (int k = kbase + threadIdx.x; k < kbase + SEGLEN; k += 256) {
            const float s = exact_score(x0, x1, x2, x3, xsv, __ldg(&emb[k]));
            const unsigned long long key = (((unsigned long long)ford_s(s)) << 32) | (unsigned)k;
            best = (key < best) ? key : best;
        }
        red[threadIdx.x] = best;
        __syncthreads();
        for (int off = 128; off > 0; off >>= 1) {
            if (threadIdx.x < off && red[threadIdx.x + off] < red[threadIdx.x])
                red[threadIdx.x] = red[threadIdx.x + off];
            __syncthreads();
        }
        if (threadIdx.x == 0)
            atomicMin(&g_fixbest[n], red[0]);
        __syncthreads();
    }
}

// ---------- kernel 4: exact lex-argmin inside winning group; slow override ----------
// Half-warp per token: 16 lanes each score one code exactly; shfl-reduce (s,k) lex-min.
__global__ void vq_final(const float* __restrict__ hs,
                         const float4* __restrict__ emb,
                         float* __restrict__ out) {
    const int lane = threadIdx.x & 31;
    const int u    = lane & 15;
    const int n    = (blockIdx.x * blockDim.x + threadIdx.x) >> 4;
    if (n >= NTOK) return;

    const unsigned int grp = (unsigned int)(g_best[n] & 0xFFFFFFFFull);
    const int kbase = (int)grp * GROUP;

    const int t = n / CH_STRIDE, hw = n % CH_STRIDE;
    float x0, x1, x2, x3;
    const float xsv = token_xs(hs + t * T_STRIDE + hw, x0, x1, x2, x3);

    const float s = exact_score(x0, x1, x2, x3, xsv, __ldg(&emb[kbase + u]));
    unsigned long long key = (((unsigned long long)ford_s(s)) << 32) | (unsigned)(kbase + u);

#pragma unroll
    for (int off = 8; off > 0; off >>= 1) {
        const unsigned long long other = __shfl_xor_sync(0xFFFFFFFFu, key, off, 16);
        key = (other < key) ? other : key;
    }
    if (u == 0) {
        const float fast_idx = (float)(unsigned int)(key & 0xFFFFFFFFull);
        const float slow_idx = (float)(unsigned int)(g_fixbest[n] & 0xFFFFFFFFull);
        out[n] = g_slow[n] ? slow_idx : fast_idx;
    }
}

extern "C" void kernel_launch(void* const* d_in, const int* in_sizes, int n_in,
                              void* d_out, int out_size) {
    // Resolve input order by element count: hidden_state 36864, embedding 131072
    const float*  hs;
    const float4* emb;
    if (in_sizes[0] == NTOK * 4) {
        hs  = (const float*)d_in[0];
        emb = (const float4*)d_in[1];
    } else {
        emb = (const float4*)d_in[0];
        hs  = (const float*)d_in[1];
    }
    float* out = (float*)d_out;

    vq_prep<<<CODEBOOK / 256, 256>>>(emb, hs);
    vq_main<<<dim3(TOKBLKS, CHUNKS, 1), TPB>>>(hs);
    vq_fix<<<dim3(NTILES, FIXSEG, 1), 256>>>(hs, emb);
    vq_final<<<(NTOK * 16 + 255) / 256, 256>>>(hs, emb, out);
}

// round 10
// speedup vs baseline: 1.8376x; 1.0051x over previous
#include <cuda_runtime.h>
#include <cstdint>

#define CODEBOOK 32768
#define NTOK     9216      // 1*4*48*48 tokens
#define CH_STRIDE 2304     // 48*48
#define T_STRIDE  9216     // 4 channels * 2304

#define TPB     128
#define TPT     8                           // tokens per thread (4 f32x2 pairs)
#define NPAIR   (TPT / 2)
#define CHUNKS  64
#define CHUNK   (CODEBOOK / CHUNKS)         // 512 codes per chunk
#define GROUP   16
#define NGROUP  (CHUNK / GROUP)             // 32 groups per chunk
#define TOKBLKS (NTOK / (TPB * TPT))        // 9 token blocks
#define FIXSEG  16                          // codebook segments for the fix pass
#define SEGLEN  (CODEBOOK / FIXSEG)         // 2048 codes per segment
#define NTILES  ((NTOK + 255) / 256)        // 36 token tiles

// Scratch (static __device__ — no allocation)
__device__ ulonglong2          g_pkA[CODEBOOK];   // (e0,e0) (e1,e1) packed f32x2
__device__ ulonglong2          g_pkB[CODEBOOK];   // (e2,e2) (e3,e3)
__device__ unsigned long long  g_best[NTOK];      // (ford(s_g) << 32) | global_group_id
__device__ unsigned long long  g_fixbest[NTOK];   // exact (ford_s(s) << 32) | k for slow tokens
__device__ unsigned int        g_slow[NTOK];      // 1 if xs < 0.125

// ---------- packed f32x2 helpers ----------
static __device__ __forceinline__ unsigned long long pack2(float lo, float hi) {
    unsigned long long r;
    asm("mov.b64 %0,{%1,%2};" : "=l"(r) : "f"(lo), "f"(hi));
    return r;
}
static __device__ __forceinline__ unsigned long long mul2(unsigned long long a, unsigned long long b) {
    unsigned long long d;
    asm("mul.rn.f32x2 %0,%1,%2;" : "=l"(d) : "l"(a), "l"(b));
    return d;
}
static __device__ __forceinline__ unsigned long long fma2(unsigned long long a, unsigned long long b,
                                                          unsigned long long c) {
    unsigned long long d;
    asm("fma.rn.f32x2 %0,%1,%2,%3;" : "=l"(d) : "l"(a), "l"(b), "l"(c));
    return d;
}
static __device__ __forceinline__ void unpack2(unsigned long long v, float& lo, float& hi) {
    asm("mov.b64 {%0,%1},%2;" : "=f"(lo), "=f"(hi) : "l"(v));
}

// main-path scores are provably positive (xs >= 0.125, |2dot| < 1e-4)
static __device__ __forceinline__ unsigned int ford(float v) {
    return __float_as_uint(v) | 0x80000000u;
}
// sign-safe total order
static __device__ __forceinline__ unsigned int ford_s(float v) {
    unsigned int b = __float_as_uint(v);
    return (b & 0x80000000u) ? ~b : (b | 0x80000000u);
}

static __device__ __forceinline__ float token_xs(const float* p, float& x0, float& x1,
                                                 float& x2, float& x3) {
    x0 = __ldg(p); x1 = __ldg(p + CH_STRIDE);
    x2 = __ldg(p + 2 * CH_STRIDE); x3 = __ldg(p + 3 * CH_STRIDE);
    return __fadd_rn(__fadd_rn(__fadd_rn(__fmul_rn(x0, x0), __fmul_rn(x1, x1)),
                               __fmul_rn(x2, x2)), __fmul_rn(x3, x3));
}

// exact reference score: s = fl(fl(xs+e2) - 2*fl_leftassoc_dot)
static __device__ __forceinline__ float exact_score(float x0, float x1, float x2, float x3,
                                                    float xs, float4 e) {
    const float e2 = __fadd_rn(__fadd_rn(__fadd_rn(__fmul_rn(e.x, e.x), __fmul_rn(e.y, e.y)),
                                         __fmul_rn(e.z, e.z)), __fmul_rn(e.w, e.w));
    const float dot = __fadd_rn(__fadd_rn(__fadd_rn(__fmul_rn(x0, e.x), __fmul_rn(x1, e.y)),
                                          __fmul_rn(x2, e.z)), __fmul_rn(x3, e.w));
    return __fmaf_rn(-2.0f, dot, __fadd_rn(xs, e2));
}

// ---------- kernel 1: codebook transform + scratch init + slow-token flags ----------
__global__ void vq_prep(const float4* __restrict__ emb, const float* __restrict__ hs) {
    int k = blockIdx.x * blockDim.x + threadIdx.x;
    if (k < NTOK) {
        g_best[k]    = ~0ull;
        g_fixbest[k] = ~0ull;
        const int t = k / CH_STRIDE, hw = k % CH_STRIDE;
        float x0, x1, x2, x3;
        const float xs = token_xs(hs + t * T_STRIDE + hw, x0, x1, x2, x3);
        // xs >= 0.125 guarantees fl(xs + e2) == xs for all codes (e2 <= 2^-28 < ulp/2)
        g_slow[k] = (xs < 0.125f) ? 1u : 0u;
    }
    if (k < CODEBOOK) {
        float4 e = __ldg(&emb[k]);
        g_pkA[k] = make_ulonglong2(pack2(e.x, e.x), pack2(e.y, e.y));
        g_pkB[k] = make_ulonglong2(pack2(e.z, e.z), pack2(e.w, e.w));
    }
}

// ---------- kernel 2: main scan (FMA-chain dot; dot-max per group) ----------
// blockIdx.x : token group (1024 tokens, 8/thread), blockIdx.y : codebook chunk (512 codes)
__global__ void __launch_bounds__(TPB) vq_main(const float* __restrict__ hs) {
    const int tid     = threadIdx.x;
    const int tokbase = blockIdx.x * (TPB * TPT);
    const int base    = blockIdx.y * CHUNK;

    float xs[TPT];
    unsigned long long X0[NPAIR], X1[NPAIR], X2[NPAIR], X3[NPAIR];
#pragma unroll
    for (int p2 = 0; p2 < NPAIR; p2++) {
        float a0, a1, a2, a3, b0, b1, b2, b3;
        {
            const int n = tokbase + (2 * p2) * TPB + tid;
            const int t = n / CH_STRIDE, hw = n % CH_STRIDE;
            xs[2 * p2] = token_xs(hs + t * T_STRIDE + hw, a0, a1, a2, a3);
        }
        {
            const int n = tokbase + (2 * p2 + 1) * TPB + tid;
            const int t = n / CH_STRIDE, hw = n % CH_STRIDE;
            xs[2 * p2 + 1] = token_xs(hs + t * T_STRIDE + hw, b0, b1, b2, b3);
        }
        X0[p2] = pack2(a0, b0); X1[p2] = pack2(a1, b1);
        X2[p2] = pack2(a2, b2); X3[p2] = pack2(a3, b3);
    }

    const float INF  = __int_as_float(0x7f800000);
    const float NINF = __int_as_float(0xff800000);

    float m[TPT];
    int   gsel[TPT];
#pragma unroll
    for (int h = 0; h < TPT; h++) { m[h] = INF; gsel[h] = 0; }

    for (int g = 0; g < NGROUP; g++) {
        float dm[TPT];
#pragma unroll
        for (int h = 0; h < TPT; h++) dm[h] = NINF;
#pragma unroll
        for (int u = 0; u < GROUP; u++) {
            const int k = base + g * GROUP + u;
            const ulonglong2 A = g_pkA[k];
            const ulonglong2 B = g_pkB[k];
#pragma unroll
            for (int p2 = 0; p2 < NPAIR; p2++) {
                // FMA-chain dot (4 packed ops). Differs from reference rounding by
                // ~1e-11 << score ulp 4.8e-7; exact argmin recovered in vq_final.
                unsigned long long d = mul2(X0[p2], A.x);
                d = fma2(X1[p2], A.y, d);
                d = fma2(X2[p2], B.x, d);
                d = fma2(X3[p2], B.y, d);
                float d0, d1;
                unpack2(d, d0, d1);
                dm[2 * p2]     = fmaxf(dm[2 * p2], d0);
                dm[2 * p2 + 1] = fmaxf(dm[2 * p2 + 1], d1);
            }
        }
#pragma unroll
        for (int h = 0; h < TPT; h++) {
            const float sg = __fmaf_rn(-2.0f, dm[h], xs[h]);   // group min score (monotone)
            if (sg < m[h]) { m[h] = sg; gsel[h] = g; }         // strict <: earliest group
        }
    }

#pragma unroll
    for (int h = 0; h < TPT; h++) {
        const int n = tokbase + h * TPB + tid;
        const unsigned long long key =
            (((unsigned long long)ford(m[h])) << 32) | (unsigned)(blockIdx.y * NGROUP + gsel[h]);
        atomicMin(&g_best[n], key);
    }
}

// ---------- kernel 3: exact rescan for slow tokens, tile x segment parallel ----------
__global__ void __launch_bounds__(256) vq_fix(const float* __restrict__ hs,
                                              const float4* __restrict__ emb) {
    __shared__ unsigned long long red[256];
    __shared__ int s_list[256];
    __shared__ int s_cnt;

    if (threadIdx.x == 0) s_cnt = 0;
    __syncthreads();

    const int n0 = blockIdx.x * 256 + threadIdx.x;
    if (n0 < NTOK && g_slow[n0]) {
        const int p = atomicAdd(&s_cnt, 1);
        s_list[p] = n0;
    }
    __syncthreads();

    const int cnt = s_cnt;
    if (cnt == 0) return;
    const int kbase = blockIdx.y * SEGLEN;

    for (int i = 0; i < cnt; i++) {
        const int n = s_list[i];
        const int t = n / CH_STRIDE, hw = n % CH_STRIDE;
        float x0, x1, x2, x3;
        const float xsv = token_xs(hs + t * T_STRIDE + hw, x0, x1, x2, x3);

        unsigned long long best = ~0ull;
#pragma unroll 4
        for (int k = kbase + threadIdx.x; k < kbase + SEGLEN; k += 256) {
            const float s = exact_score(x0, x1, x2, x3, xsv, __ldg(&emb[k]));
            const unsigned long long key = (((unsigned long long)ford_s(s)) << 32) | (unsigned)k;
            best = (key < best) ? key : best;
        }
        red[threadIdx.x] = best;
        __syncthreads();
        for (int off = 128; off > 0; off >>= 1) {
            if (threadIdx.x < off && red[threadIdx.x + off] < red[threadIdx.x])
                red[threadIdx.x] = red[threadIdx.x + off];
            __syncthreads();
        }
        if (threadIdx.x == 0)
            atomicMin(&g_fixbest[n], red[0]);
        __syncthreads();
    }
}

// ---------- kernel 4: exact lex-argmin inside winning group; slow override ----------
// Half-warp per token: 16 lanes each score one code exactly; shfl-reduce (s,k) lex-min.
__global__ void vq_final(const float* __restrict__ hs,
                         const float4* __restrict__ emb,
                         float* __restrict__ out) {
    const int lane = threadIdx.x & 31;
    const int u    = lane & 15;
    const int n    = (blockIdx.x * blockDim.x + threadIdx.x) >> 4;
    if (n >= NTOK) return;

    const unsigned int grp = (unsigned int)(g_best[n] & 0xFFFFFFFFull);
    const int kbase = (int)grp * GROUP;

    const int t = n / CH_STRIDE, hw = n % CH_STRIDE;
    float x0, x1, x2, x3;
    const float xsv = token_xs(hs + t * T_STRIDE + hw, x0, x1, x2, x3);

    const float s = exact_score(x0, x1, x2, x3, xsv, __ldg(&emb[kbase + u]));
    unsigned long long key = (((unsigned long long)ford_s(s)) << 32) | (unsigned)(kbase + u);

#pragma unroll
    for (int off = 8; off > 0; off >>= 1) {
        const unsigned long long other = __shfl_xor_sync(0xFFFFFFFFu, key, off, 16);
        key = (other < key) ? other : key;
    }
    if (u == 0) {
        const float fast_idx = (float)(unsigned int)(key & 0xFFFFFFFFull);
        const float slow_idx = (float)(unsigned int)(g_fixbest[n] & 0xFFFFFFFFull);
        out[n] = g_slow[n] ? slow_idx : fast_idx;
    }
}

extern "C" void kernel_launch(void* const* d_in, const int* in_sizes, int n_in,
                              void* d_out, int out_size) {
    // Resolve input order by element count: hidden_state 36864, embedding 131072
    const float*  hs;
    const float4* emb;
    if (in_sizes[0] == NTOK * 4) {
        hs  = (const float*)d_in[0];
        emb = (const float4*)d_in[1];
    } else {
        emb = (const float4*)d_in[0];
        hs  = (const float*)d_in[1];
    }
    float* out = (float*)d_out;

    vq_prep<<<CODEBOOK / 256, 256>>>(emb, hs);
    vq_main<<<dim3(TOKBLKS, CHUNKS, 1), TPB>>>(hs);
    vq_fix<<<dim3(NTILES, FIXSEG, 1), 256>>>(hs, emb);
    vq_final<<<(NTOK * 16 + 255) / 256, 256>>>(hs, emb, out);
}

// round 11
// speedup vs baseline: 2.1238x; 1.1558x over previous
#include <cuda_runtime.h>
#include <cstdint>

#define CODEBOOK 32768
#define NTOK     9216      // 1*4*48*48 tokens
#define CH_STRIDE 2304     // 48*48
#define T_STRIDE  9216     // 4 channels * 2304

#define TPB     128
#define TPT     8                           // tokens per thread (4 f32x2 pairs)
#define NPAIR   (TPT / 2)
#define CHUNKS  64
#define CHUNK   (CODEBOOK / CHUNKS)         // 512 codes per chunk
#define GROUP   16
#define NGROUP  (CHUNK / GROUP)             // 32 groups per chunk
#define TOKBLKS (NTOK / (TPB * TPT))        // 9 token blocks
#define FIXSEG  16                          // codebook segments for the fix pass
#define SEGLEN  (CODEBOOK / FIXSEG)         // 2048 codes per segment
#define NTILES  ((NTOK + 255) / 256)        // 36 token tiles

// Scratch (static __device__ — no allocation, plain stores, no init required)
__device__ unsigned long long g_part[CHUNKS * NTOK];    // per-chunk (ford(s)<<32)|group keys
__device__ unsigned long long g_fixpart[FIXSEG * NTOK]; // per-segment exact keys (slow tokens)

// ---------- packed f32x2 helpers ----------
static __device__ __forceinline__ unsigned long long pack2(float lo, float hi) {
    unsigned long long r;
    asm("mov.b64 %0,{%1,%2};" : "=l"(r) : "f"(lo), "f"(hi));
    return r;
}
static __device__ __forceinline__ unsigned long long mul2(unsigned long long a, unsigned long long b) {
    unsigned long long d;
    asm("mul.rn.f32x2 %0,%1,%2;" : "=l"(d) : "l"(a), "l"(b));
    return d;
}
static __device__ __forceinline__ unsigned long long fma2(unsigned long long a, unsigned long long b,
                                                          unsigned long long c) {
    unsigned long long d;
    asm("fma.rn.f32x2 %0,%1,%2,%3;" : "=l"(d) : "l"(a), "l"(b), "l"(c));
    return d;
}
static __device__ __forceinline__ void unpack2(unsigned long long v, float& lo, float& hi) {
    asm("mov.b64 {%0,%1},%2;" : "=f"(lo), "=f"(hi) : "l"(v));
}

// main-path scores are provably positive (xs >= 0.125, |2dot| < 1e-4)
static __device__ __forceinline__ unsigned int ford(float v) {
    return __float_as_uint(v) | 0x80000000u;
}
// sign-safe total order (slow path)
static __device__ __forceinline__ unsigned int ford_s(float v) {
    unsigned int b = __float_as_uint(v);
    return (b & 0x80000000u) ? ~b : (b | 0x80000000u);
}

static __device__ __forceinline__ float token_xs(const float* p, float& x0, float& x1,
                                                 float& x2, float& x3) {
    x0 = __ldg(p); x1 = __ldg(p + CH_STRIDE);
    x2 = __ldg(p + 2 * CH_STRIDE); x3 = __ldg(p + 3 * CH_STRIDE);
    return __fadd_rn(__fadd_rn(__fadd_rn(__fmul_rn(x0, x0), __fmul_rn(x1, x1)),
                               __fmul_rn(x2, x2)), __fmul_rn(x3, x3));
}

// exact reference score: s = fl(fl(xs+e2) - 2*fl_leftassoc_dot)
static __device__ __forceinline__ float exact_score(float x0, float x1, float x2, float x3,
                                                    float xs, float4 e) {
    const float e2 = __fadd_rn(__fadd_rn(__fadd_rn(__fmul_rn(e.x, e.x), __fmul_rn(e.y, e.y)),
                                         __fmul_rn(e.z, e.z)), __fmul_rn(e.w, e.w));
    const float dot = __fadd_rn(__fadd_rn(__fadd_rn(__fmul_rn(x0, e.x), __fmul_rn(x1, e.y)),
                                          __fmul_rn(x2, e.z)), __fmul_rn(x3, e.w));
    return __fmaf_rn(-2.0f, dot, __fadd_rn(xs, e2));
}

// ---------- kernel 1: main scan (raw codebook load, in-register packing) ----------
// blockIdx.x : token group (1024 tokens, 8/thread), blockIdx.y : codebook chunk (512 codes)
__global__ void __launch_bounds__(TPB) vq_main(const float* __restrict__ hs,
                                               const float4* __restrict__ emb) {
    const int tid     = threadIdx.x;
    const int tokbase = blockIdx.x * (TPB * TPT);
    const int base    = blockIdx.y * CHUNK;

    float xs[TPT];
    unsigned long long X0[NPAIR], X1[NPAIR], X2[NPAIR], X3[NPAIR];
#pragma unroll
    for (int p2 = 0; p2 < NPAIR; p2++) {
        float a0, a1, a2, a3, b0, b1, b2, b3;
        {
            const int n = tokbase + (2 * p2) * TPB + tid;
            const int t = n / CH_STRIDE, hw = n % CH_STRIDE;
            xs[2 * p2] = token_xs(hs + t * T_STRIDE + hw, a0, a1, a2, a3);
        }
        {
            const int n = tokbase + (2 * p2 + 1) * TPB + tid;
            const int t = n / CH_STRIDE, hw = n % CH_STRIDE;
            xs[2 * p2 + 1] = token_xs(hs + t * T_STRIDE + hw, b0, b1, b2, b3);
        }
        X0[p2] = pack2(a0, b0); X1[p2] = pack2(a1, b1);
        X2[p2] = pack2(a2, b2); X3[p2] = pack2(a3, b3);
    }

    const float INF  = __int_as_float(0x7f800000);
    const float NINF = __int_as_float(0xff800000);

    float m[TPT];
    int   gsel[TPT];
#pragma unroll
    for (int h = 0; h < TPT; h++) { m[h] = INF; gsel[h] = 0; }

    for (int g = 0; g < NGROUP; g++) {
        float dm[TPT];
#pragma unroll
        for (int h = 0; h < TPT; h++) dm[h] = NINF;
#pragma unroll
        for (int u = 0; u < GROUP; u++) {
            const float4 e = __ldg(&emb[base + g * GROUP + u]);
            const unsigned long long A0 = pack2(e.x, e.x);
            const unsigned long long A1 = pack2(e.y, e.y);
            const unsigned long long B0 = pack2(e.z, e.z);
            const unsigned long long B1 = pack2(e.w, e.w);
#pragma unroll
            for (int p2 = 0; p2 < NPAIR; p2++) {
                // FMA-chain dot (approx vs reference by ~1e-11 << score ulp; exact
                // argmin recovered in vq_final's group rescan)
                unsigned long long d = mul2(X0[p2], A0);
                d = fma2(X1[p2], A1, d);
                d = fma2(X2[p2], B0, d);
                d = fma2(X3[p2], B1, d);
                float d0, d1;
                unpack2(d, d0, d1);
                dm[2 * p2]     = fmaxf(dm[2 * p2], d0);
                dm[2 * p2 + 1] = fmaxf(dm[2 * p2 + 1], d1);
            }
        }
#pragma unroll
        for (int h = 0; h < TPT; h++) {
            const float sg = __fmaf_rn(-2.0f, dm[h], xs[h]);   // group min score (monotone)
            if (sg < m[h]) { m[h] = sg; gsel[h] = g; }         // strict <: earliest group
        }
    }

    // plain store (no init needed): one slot per (chunk, token)
#pragma unroll
    for (int h = 0; h < TPT; h++) {
        const int n = tokbase + h * TPB + tid;
        g_part[blockIdx.y * NTOK + n] =
            (((unsigned long long)ford(m[h])) << 32) | (unsigned)(blockIdx.y * NGROUP + gsel[h]);
    }
}

// ---------- kernel 2: exact per-segment scan for slow tokens (xs < 0.125) ----------
// Block (tile, seg): compute slow flags locally, collect, scan 2048-code segment.
__global__ void __launch_bounds__(256) vq_fix(const float* __restrict__ hs,
                                              const float4* __restrict__ emb) {
    __shared__ unsigned long long red[256];
    __shared__ int s_list[256];
    __shared__ int s_cnt;

    if (threadIdx.x == 0) s_cnt = 0;
    __syncthreads();

    const int n0 = blockIdx.x * 256 + threadIdx.x;
    if (n0 < NTOK) {
        const int t = n0 / CH_STRIDE, hw = n0 % CH_STRIDE;
        float x0, x1, x2, x3;
        const float xs = token_xs(hs + t * T_STRIDE + hw, x0, x1, x2, x3);
        // xs >= 0.125 guarantees fl(xs + e2) == xs for all codes (e2 <= 2^-28 < ulp/2)
        if (xs < 0.125f) {
            const int p = atomicAdd(&s_cnt, 1);
            s_list[p] = n0;
        }
    }
    __syncthreads();

    const int cnt = s_cnt;
    if (cnt == 0) return;
    const int kbase = blockIdx.y * SEGLEN;

    for (int i = 0; i < cnt; i++) {
        const int n = s_list[i];
        const int t = n / CH_STRIDE, hw = n % CH_STRIDE;
        float x0, x1, x2, x3;
        const float xsv = token_xs(hs + t * T_STRIDE + hw, x0, x1, x2, x3);

        unsigned long long best = ~0ull;
#pragma unroll 4
        for (int k = kbase + threadIdx.x; k < kbase + SEGLEN; k += 256) {
            const float s = exact_score(x0, x1, x2, x3, xsv, __ldg(&emb[k]));
            const unsigned long long key = (((unsigned long long)ford_s(s)) << 32) | (unsigned)k;
            best = (key < best) ? key : best;
        }
        red[threadIdx.x] = best;
        __syncthreads();
        for (int off = 128; off > 0; off >>= 1) {
            if (threadIdx.x < off && red[threadIdx.x + off] < red[threadIdx.x])
                red[threadIdx.x] = red[threadIdx.x + off];
            __syncthreads();
        }
        if (threadIdx.x == 0)
            g_fixpart[blockIdx.y * NTOK + n] = red[0];   // plain store, only slow tokens read
        __syncthreads();
    }
}

// ---------- kernel 3: merge chunk keys + exact in-group argmin; slow override ----------
// Half-warp per token (16 lanes), two tokens per warp (shfl width 16 keeps them apart).
__global__ void vq_final(const float* __restrict__ hs,
                         const float4* __restrict__ emb,
                         float* __restrict__ out) {
    const int lane = threadIdx.x & 31;
    const int u    = lane & 15;
    const int n    = (blockIdx.x * blockDim.x + threadIdx.x) >> 4;
    if (n >= NTOK) return;

    const int t = n / CH_STRIDE, hw = n % CH_STRIDE;
    float x0, x1, x2, x3;
    const float xsv = token_xs(hs + t * T_STRIDE + hw, x0, x1, x2, x3);

    if (xsv >= 0.125f) {
        // merge the 64 per-chunk keys: lane u covers chunks u, u+16, u+32, u+48
        unsigned long long key = ~0ull;
#pragma unroll
        for (int j = 0; j < CHUNKS / 16; j++) {
            const unsigned long long v = g_part[(u + 16 * j) * NTOK + n];
            key = (v < key) ? v : key;
        }
#pragma unroll
        for (int off = 8; off > 0; off >>= 1) {
            const unsigned long long other = __shfl_xor_sync(0xFFFFFFFFu, key, off, 16);
            key = (other < key) ? other : key;
        }
        const int kbase = (int)(unsigned int)(key & 0xFFFFFFFFull) * GROUP;

        // exact lex-argmin inside the winning 16-code group
        const float s = exact_score(x0, x1, x2, x3, xsv, __ldg(&emb[kbase + u]));
        unsigned long long k2 = (((unsigned long long)ford_s(s)) << 32) | (unsigned)(kbase + u);
#pragma unroll
        for (int off = 8; off > 0; off >>= 1) {
            const unsigned long long other = __shfl_xor_sync(0xFFFFFFFFu, k2, off, 16);
            k2 = (other < k2) ? other : k2;
        }
        if (u == 0) out[n] = (float)(unsigned int)(k2 & 0xFFFFFFFFull);
    } else {
        // slow token: merge the 16 exact per-segment keys
        unsigned long long key = g_fixpart[u * NTOK + n];
#pragma unroll
        for (int off = 8; off > 0; off >>= 1) {
            const unsigned long long other = __shfl_xor_sync(0xFFFFFFFFu, key, off, 16);
            key = (other < key) ? other : key;
        }
        if (u == 0) out[n] = (float)(unsigned int)(key & 0xFFFFFFFFull);
    }
}

extern "C" void kernel_launch(void* const* d_in, const int* in_sizes, int n_in,
                              void* d_out, int out_size) {
    // Resolve input order by element count: hidden_state 36864, embedding 131072
    const float*  hs;
    const float4* emb;
    if (in_sizes[0] == NTOK * 4) {
        hs  = (const float*)d_in[0];
        emb = (const float4*)d_in[1];
    } else {
        emb = (const float4*)d_in[0];
        hs  = (const float*)d_in[1];
    }
    float* out = (float*)d_out;

    vq_main<<<dim3(TOKBLKS, CHUNKS, 1), TPB>>>(hs, emb);
    vq_fix<<<dim3(NTILES, FIXSEG, 1), 256>>>(hs, emb);
    vq_final<<<(NTOK * 16 + 255) / 256, 256>>>(hs, emb, out);
}